// round 2
// baseline (speedup 1.0000x reference)
#include <cuda_runtime.h>
#include <cuda_bf16.h>
#include <math.h>
#include <stddef.h>

// ---------------- problem constants ----------------
#define SEQ      33600
#define DMODEL   256
#define NHEADS   8
#define NLEVELS  3
#define NPOINTS  4
#define LP       (NLEVELS * NPOINTS)        // 12
#define HD       (DMODEL / NHEADS)          // 32
#define NOFF     (NHEADS * LP * 2)          // 192
#define NATT     (NHEADS * LP)              // 96
#define N2       (NOFF + NATT)              // 288
#define OUT_ELEMS  ((size_t)SEQ * DMODEL)           // 8601600
#define ATTN_ELEMS ((size_t)SEQ * NHEADS * LP)      // 3225600

// ---------------- scratch (device globals; no allocs allowed) ----------------
__device__ float g_value[SEQ * DMODEL];   // value = enc @ Wv^T + bv
__device__ float g_raw  [SEQ * N2];       // [offsets(192) | attn logits(96)] per query
__device__ float g_samp [SEQ * DMODEL];   // sampled+weighted output before Wo
__device__ float g_w2   [N2 * DMODEL];    // combined [Ws; Wa]
__device__ float g_b2   [N2];

// ---------------- tiny kernel: combine Ws/Wa into one weight ----------------
__global__ void build_w2_kernel(const float* __restrict__ Ws, const float* __restrict__ bs,
                                const float* __restrict__ Wa, const float* __restrict__ ba) {
    int i = blockIdx.x * blockDim.x + threadIdx.x;
    if (i < N2 * DMODEL) {
        int n = i / DMODEL;
        g_w2[i] = (n < NOFF) ? Ws[i] : Wa[i - NOFF * DMODEL];
    }
    if (i < N2) g_b2[i] = (i < NOFF) ? bs[i] : ba[i - NOFF];
}

// ---------------- fp32 SGEMM: C[M,N] = (A (+A2)) @ W^T + bias ----------------
// A: [M,K] row-major; W: [N,K] row-major; block tile 128x64, BK=16, 256 threads,
// each thread computes 8x4 outputs.
#define BM 128
#define BN 64
#define BKK 16
#define TM 8
#define TN 4

__global__ __launch_bounds__(256) void sgemm_kernel(
    const float* __restrict__ A, const float* __restrict__ A2,
    const float* __restrict__ W, const float* __restrict__ bias,
    float* __restrict__ C, int M, int N, int K)
{
    __shared__ __align__(16) float As[BKK][BM + 4];
    __shared__ __align__(16) float Bs[BKK][BN];

    const int tid = threadIdx.x;
    const int block_m = blockIdx.y * BM;
    const int block_n = blockIdx.x * BN;

    const int tn = tid & 15;        // 0..15 (n dim)
    const int tm = tid >> 4;        // 0..15 (m dim)

    // loader mapping: 4 float4 per 16-wide K row
    const int a_vrow = tid >> 2;          // 0..63
    const int a_vcol = (tid & 3) * 4;     // 0,4,8,12

    float acc[TM][TN];
    #pragma unroll
    for (int i = 0; i < TM; i++)
        #pragma unroll
        for (int j = 0; j < TN; j++) acc[i][j] = 0.f;

    for (int k0 = 0; k0 < K; k0 += BKK) {
        // ---- load A tile (128x16): 2 passes of 64 rows ----
        #pragma unroll
        for (int r = 0; r < BM; r += 64) {
            int ml = a_vrow + r;
            int m  = block_m + ml;
            float4 v = make_float4(0.f, 0.f, 0.f, 0.f);
            if (m < M) {
                v = *(const float4*)(A + (size_t)m * K + k0 + a_vcol);
                if (A2) {
                    float4 v2 = *(const float4*)(A2 + (size_t)m * K + k0 + a_vcol);
                    v.x += v2.x; v.y += v2.y; v.z += v2.z; v.w += v2.w;
                }
            }
            As[a_vcol + 0][ml] = v.x;
            As[a_vcol + 1][ml] = v.y;
            As[a_vcol + 2][ml] = v.z;
            As[a_vcol + 3][ml] = v.w;
        }
        // ---- load B tile (64x16) ----
        {
            int nl = a_vrow;            // 0..63
            int n  = block_n + nl;
            float4 v = make_float4(0.f, 0.f, 0.f, 0.f);
            if (n < N) v = *(const float4*)(W + (size_t)n * K + k0 + a_vcol);
            Bs[a_vcol + 0][nl] = v.x;
            Bs[a_vcol + 1][nl] = v.y;
            Bs[a_vcol + 2][nl] = v.z;
            Bs[a_vcol + 3][nl] = v.w;
        }
        __syncthreads();

        #pragma unroll
        for (int kk = 0; kk < BKK; kk++) {
            float4 a0 = *(const float4*)&As[kk][tm * TM];
            float4 a1 = *(const float4*)&As[kk][tm * TM + 4];
            float4 b0 = *(const float4*)&Bs[kk][tn * TN];
            float a[TM] = {a0.x, a0.y, a0.z, a0.w, a1.x, a1.y, a1.z, a1.w};
            float b[TN] = {b0.x, b0.y, b0.z, b0.w};
            #pragma unroll
            for (int i = 0; i < TM; i++)
                #pragma unroll
                for (int j = 0; j < TN; j++)
                    acc[i][j] = fmaf(a[i], b[j], acc[i][j]);
        }
        __syncthreads();
    }

    // ---- store ----
    #pragma unroll
    for (int i = 0; i < TM; i++) {
        int m = block_m + tm * TM + i;
        if (m >= M) continue;
        #pragma unroll
        for (int j = 0; j < TN; j++) {
            int n = block_n + tn * TN + j;
            if (n < N) C[(size_t)m * N + n] = acc[i][j] + bias[n];
        }
    }
}

// ---------------- sampling: softmax + bilinear gather + weighted sum ----------------
// block = one query, 256 threads: warp h = head, lane = channel (hd=32)
__global__ __launch_bounds__(256) void sample_kernel(
    const float* __restrict__ value,       // [SEQ, 256]
    const float* __restrict__ raw,         // [SEQ, 288]
    const float* __restrict__ refp,        // [SEQ, 3, 2]
    float* __restrict__ out,               // [SEQ, 256]
    float* __restrict__ attn_out)          // [SEQ, 8, 12] or null
{
    const int q    = blockIdx.x;
    const int tid  = threadIdx.x;
    const int h    = tid >> 5;
    const int lane = tid & 31;

    __shared__ float s_a [NHEADS * LP];
    __shared__ float s_px[NHEADS * LP];
    __shared__ float s_py[NHEADS * LP];

    const float* rq = raw + (size_t)q * N2;

    // softmax over LP=12 logits for this head
    float logit = (lane < LP) ? rq[NOFF + h * LP + lane] : -INFINITY;
    float m = logit;
    #pragma unroll
    for (int o = 16; o; o >>= 1) m = fmaxf(m, __shfl_xor_sync(0xffffffffu, m, o));
    float e = (lane < LP) ? expf(logit - m) : 0.f;
    float s = e;
    #pragma unroll
    for (int o = 16; o; o >>= 1) s += __shfl_xor_sync(0xffffffffu, s, o);
    float wgt = e / s;

    if (lane < LP) {
        s_a[h * LP + lane] = wgt;
        if (attn_out) attn_out[((size_t)q * NHEADS + h) * LP + lane] = wgt;

        const int l = lane >> 2;                // level
        const float dim = (float)(160 >> l);    // square levels: W==H
        const float ox = rq[(h * LP + lane) * 2 + 0];
        const float oy = rq[(h * LP + lane) * 2 + 1];
        const float rx = refp[((size_t)q * NLEVELS + l) * 2 + 0];
        const float ry = refp[((size_t)q * NLEVELS + l) * 2 + 1];
        const float locx = rx + ox / dim;       // norm = [w, h] per level
        const float locy = ry + oy / dim;
        s_px[h * LP + lane] = locx * dim - 0.5f;
        s_py[h * LP + lane] = locy * dim - 0.5f;
    }
    __syncwarp();

    float acc = 0.f;
    #pragma unroll
    for (int lp = 0; lp < LP; lp++) {
        const int l     = lp >> 2;
        const int Wi    = 160 >> l;
        const int start = (l == 0) ? 0 : ((l == 1) ? 25600 : 32000);

        const float a  = s_a [h * LP + lp];
        const float px = s_px[h * LP + lp];
        const float py = s_py[h * LP + lp];

        const float x0f = floorf(px), y0f = floorf(py);
        const int   x0  = (int)x0f,   y0  = (int)y0f;
        const float wx1 = px - x0f, wy1 = py - y0f;
        const float wx0 = 1.f - wx1, wy0 = 1.f - wy1;

        const bool xok0 = (x0 >= 0)     && (x0 < Wi);
        const bool xok1 = (x0 >= -1)    && (x0 + 1 < Wi);
        const bool yok0 = (y0 >= 0)     && (y0 < Wi);     // square: Hi==Wi
        const bool yok1 = (y0 >= -1)    && (y0 + 1 < Wi);

        const float* vb = value + (size_t)start * DMODEL + h * HD + lane;

        float v00 = 0.f, v10 = 0.f, v01 = 0.f, v11 = 0.f;
        if (xok0 && yok0) v00 = vb[(size_t)(y0 * Wi + x0) * DMODEL];
        if (xok1 && yok0) v10 = vb[(size_t)(y0 * Wi + x0 + 1) * DMODEL];
        if (xok0 && yok1) v01 = vb[(size_t)((y0 + 1) * Wi + x0) * DMODEL];
        if (xok1 && yok1) v11 = vb[(size_t)((y0 + 1) * Wi + x0 + 1) * DMODEL];

        acc = fmaf(a, wy0 * (wx0 * v00 + wx1 * v10) + wy1 * (wx0 * v01 + wx1 * v11), acc);
    }

    out[(size_t)q * DMODEL + h * HD + lane] = acc;
}

// ---------------- launch ----------------
extern "C" void kernel_launch(void* const* d_in, const int* in_sizes, int n_in,
                              void* d_out, int out_size)
{
    const float* hidden = (const float*)d_in[0];
    const float* enc    = (const float*)d_in[1];
    const float* pos    = (const float*)d_in[2];
    const float* refp   = (const float*)d_in[3];
    const float* Wv     = (const float*)d_in[4];
    const float* bv     = (const float*)d_in[5];
    const float* Ws     = (const float*)d_in[6];
    const float* bs     = (const float*)d_in[7];
    const float* Wa     = (const float*)d_in[8];
    const float* ba     = (const float*)d_in[9];
    const float* Wo     = (const float*)d_in[10];
    const float* bo     = (const float*)d_in[11];

    float* out = (float*)d_out;
    float* attn_ptr = ((size_t)out_size >= OUT_ELEMS + ATTN_ELEMS) ? (out + OUT_ELEMS) : nullptr;

    float *p_value, *p_raw, *p_samp, *p_w2, *p_b2;
    cudaGetSymbolAddress((void**)&p_value, g_value);
    cudaGetSymbolAddress((void**)&p_raw,   g_raw);
    cudaGetSymbolAddress((void**)&p_samp,  g_samp);
    cudaGetSymbolAddress((void**)&p_w2,    g_w2);
    cudaGetSymbolAddress((void**)&p_b2,    g_b2);

    // 1) combined offset/attn weight
    build_w2_kernel<<<(N2 * DMODEL + 255) / 256, 256>>>(Ws, bs, Wa, ba);

    const int grid_m = (SEQ + BM - 1) / BM;   // 263

    // 2) value = enc @ Wv^T + bv
    {
        dim3 g(DMODEL / BN, grid_m);
        sgemm_kernel<<<g, 256>>>(enc, nullptr, Wv, bv, p_value, SEQ, DMODEL, DMODEL);
    }
    // 3) raw = (hidden + pos) @ [Ws;Wa]^T + [bs;ba]
    {
        dim3 g((N2 + BN - 1) / BN, grid_m);
        sgemm_kernel<<<g, 256>>>(hidden, pos, p_w2, p_b2, p_raw, SEQ, N2, DMODEL);
    }
    // 4) softmax + deformable sampling
    sample_kernel<<<SEQ, 256>>>(p_value, p_raw, refp, p_samp, attn_ptr);

    // 5) output = samp @ Wo^T + bo  (directly into d_out)
    {
        dim3 g(DMODEL / BN, grid_m);
        sgemm_kernel<<<g, 256>>>(p_samp, nullptr, Wo, bo, out, SEQ, DMODEL, DMODEL);
    }
}

// round 4
// speedup vs baseline: 2.5478x; 2.5478x over previous
#include <cuda_runtime.h>
#include <cuda_bf16.h>
#include <math.h>
#include <stddef.h>
#include <stdint.h>

// ---------------- problem constants ----------------
#define SEQ      33600
#define DMODEL   256
#define NHEADS   8
#define NLEVELS  3
#define NPOINTS  4
#define LP       (NLEVELS * NPOINTS)        // 12
#define HD       (DMODEL / NHEADS)          // 32
#define NOFF     (NHEADS * LP * 2)          // 192
#define NATT     (NHEADS * LP)              // 96
#define N2       (NOFF + NATT)              // 288
#define KHL      512                         // hi|lo K width (2*256)
#define OUT_ELEMS  ((size_t)SEQ * DMODEL)           // 8601600
#define ATTN_ELEMS ((size_t)SEQ * NHEADS * LP)      // 3225600

// ---------------- scratch (device globals; no allocs allowed) ----------------
__device__ float g_value[SEQ * DMODEL];           // value (fp32, for sampling)
__device__ float g_raw  [SEQ * N2];               // offsets + logits (fp32)
__device__ float g_w2   [N2 * DMODEL];            // combined [Ws; Wa] fp32
__device__ float g_b2   [N2];
__device__ __nv_bfloat16 g_encb [SEQ * KHL];      // enc        hi|lo
__device__ __nv_bfloat16 g_hsb  [SEQ * KHL];      // hidden+pos hi|lo
__device__ __nv_bfloat16 g_sampb[SEQ * KHL];      // sampled    hi|lo
__device__ __nv_bfloat16 g_wvb  [DMODEL * KHL];
__device__ __nv_bfloat16 g_w2b  [N2 * KHL];
__device__ __nv_bfloat16 g_wob  [DMODEL * KHL];

// ---------------- helpers ----------------
__device__ __forceinline__ uint32_t pack_bf2(__nv_bfloat16 a, __nv_bfloat16 b) {
    __nv_bfloat162 t = __halves2bfloat162(a, b);
    return *reinterpret_cast<uint32_t*>(&t);
}
__device__ __forceinline__ void split_bf16(float x, __nv_bfloat16& h, __nv_bfloat16& l) {
    h = __float2bfloat16_rn(x);
    l = __float2bfloat16_rn(x - __bfloat162float(h));
}

// ---------------- combine Ws/Wa ----------------
__global__ void build_w2_kernel(const float* __restrict__ Ws, const float* __restrict__ bs,
                                const float* __restrict__ Wa, const float* __restrict__ ba) {
    int i = blockIdx.x * blockDim.x + threadIdx.x;
    if (i < N2 * DMODEL) {
        int n = i / DMODEL;
        g_w2[i] = (n < NOFF) ? Ws[i] : Wa[i - NOFF * DMODEL];
    }
    if (i < N2) g_b2[i] = (i < NOFF) ? bs[i] : ba[i - NOFF];
}

// ---------------- fp32 -> bf16 hi|lo conversion (K=256 fixed) ----------------
__global__ __launch_bounds__(256) void conv_hilo_kernel(
    const float* __restrict__ X, const float* __restrict__ X2,
    __nv_bfloat16* __restrict__ Y, int rows)
{
    int t = blockIdx.x * 256 + threadIdx.x;
    if (t >= rows * 64) return;
    int row = t >> 6, c4 = t & 63;
    float4 v = *(const float4*)(X + (size_t)row * DMODEL + c4 * 4);
    if (X2) {
        float4 u = *(const float4*)(X2 + (size_t)row * DMODEL + c4 * 4);
        v.x += u.x; v.y += u.y; v.z += u.z; v.w += u.w;
    }
    __nv_bfloat16 h0, h1, h2, h3, l0, l1, l2, l3;
    split_bf16(v.x, h0, l0); split_bf16(v.y, h1, l1);
    split_bf16(v.z, h2, l2); split_bf16(v.w, h3, l3);
    uint2 H = make_uint2(pack_bf2(h0, h1), pack_bf2(h2, h3));
    uint2 L = make_uint2(pack_bf2(l0, l1), pack_bf2(l2, l3));
    *(uint2*)(Y + (size_t)row * KHL + c4 * 4)          = H;
    *(uint2*)(Y + (size_t)row * KHL + DMODEL + c4 * 4) = L;
}

// ---------------- bf16 mma.sync GEMM with hi/lo compensation ----------------
// C[M,N] = A[M,K=256] @ B[N,K]^T + bias, computed as Ah·Bh + Ah·Bl + Al·Bh.
// A,B stored as [rows, 512] bf16 = [hi(256) | lo(256)].
// CTA 256 threads, tile 128x128, K-chunk 64; warps 4(m) x 2(n), warp tile 32x64.
__global__ __launch_bounds__(256, 1) void gemm_bf16_kernel(
    const __nv_bfloat16* __restrict__ A,
    const __nv_bfloat16* __restrict__ B,
    const float* __restrict__ bias,
    float* __restrict__ C, int M, int N)
{
    __shared__ __align__(16) __nv_bfloat16 As[128 * 64];
    __shared__ __align__(16) __nv_bfloat16 Bs[128 * 64];

    const int tid = threadIdx.x;
    const int wid = tid >> 5, lane = tid & 31;
    const int warp_m = wid & 3, warp_n = wid >> 2;
    const int blk_m = blockIdx.y * 128, blk_n = blockIdx.x * 128;

    const uint32_t as_base = (uint32_t)__cvta_generic_to_shared(As);
    const uint32_t bs_base = (uint32_t)__cvta_generic_to_shared(Bs);

    // loader mapping: 1024 16B-chunks per tile / 256 threads = 4 each
    int lrow[4], lkc[4];
    uint32_t s_off[4];
    #pragma unroll
    for (int i = 0; i < 4; i++) {
        int id = tid + 256 * i;
        lrow[i] = id >> 3; lkc[i] = id & 7;
        s_off[i] = (uint32_t)(lrow[i] * 128 + ((lkc[i] ^ (lrow[i] & 7)) << 4));
    }

    float acc[2][8][4];
    #pragma unroll
    for (int a = 0; a < 2; a++)
        #pragma unroll
        for (int b = 0; b < 8; b++)
            #pragma unroll
            for (int c = 0; c < 4; c++) acc[a][b][c] = 0.f;

    int4 pa[4], pb[4];
    const int4 Z = make_int4(0, 0, 0, 0);

    // prefetch chunk 0
    {
        const int acol = 0, bcol = 0;
        #pragma unroll
        for (int i = 0; i < 4; i++) {
            int am = blk_m + lrow[i];
            pa[i] = (am < M) ? *(const int4*)(A + (size_t)am * KHL + acol + lkc[i] * 8) : Z;
            int bn = blk_n + lrow[i];
            pb[i] = (bn < N) ? *(const int4*)(B + (size_t)bn * KHL + bcol + lkc[i] * 8) : Z;
        }
    }

    for (int c = 0; c < 12; c++) {
        // store prefetched tile
        #pragma unroll
        for (int i = 0; i < 4; i++) {
            *(int4*)((char*)As + s_off[i]) = pa[i];
            *(int4*)((char*)Bs + s_off[i]) = pb[i];
        }
        __syncthreads();

        // prefetch next chunk
        if (c < 11) {
            int nc = c + 1;
            int pass = nc >> 2, kk = (nc & 3) * 64;
            int acol = ((pass == 2) ? DMODEL : 0) + kk;
            int bcol = ((pass == 1) ? DMODEL : 0) + kk;
            #pragma unroll
            for (int i = 0; i < 4; i++) {
                int am = blk_m + lrow[i];
                pa[i] = (am < M) ? *(const int4*)(A + (size_t)am * KHL + acol + lkc[i] * 8) : Z;
                int bn = blk_n + lrow[i];
                pb[i] = (bn < N) ? *(const int4*)(B + (size_t)bn * KHL + bcol + lkc[i] * 8) : Z;
            }
        }

        // compute: 4 k-steps of 16
        const int t4 = lane >> 3, r8 = lane & 7;
        #pragma unroll
        for (int ks = 0; ks < 4; ks++) {
            uint32_t af[2][4];
            #pragma unroll
            for (int mi = 0; mi < 2; mi++) {
                int row = warp_m * 32 + mi * 16 + (t4 & 1) * 8 + r8;
                int kch = ks * 2 + (t4 >> 1);
                uint32_t addr = as_base + (uint32_t)(row * 128 + ((kch ^ (row & 7)) << 4));
                asm volatile("ldmatrix.sync.aligned.m8n8.x4.shared.b16 {%0,%1,%2,%3}, [%4];"
                             : "=r"(af[mi][0]), "=r"(af[mi][1]), "=r"(af[mi][2]), "=r"(af[mi][3])
                             : "r"(addr));
            }
            uint32_t bf[4][4];
            #pragma unroll
            for (int j = 0; j < 4; j++) {
                int nrow = warp_n * 64 + j * 16 + (t4 >> 1) * 8 + r8;
                int kch = ks * 2 + (t4 & 1);
                uint32_t addr = bs_base + (uint32_t)(nrow * 128 + ((kch ^ (nrow & 7)) << 4));
                asm volatile("ldmatrix.sync.aligned.m8n8.x4.shared.b16 {%0,%1,%2,%3}, [%4];"
                             : "=r"(bf[j][0]), "=r"(bf[j][1]), "=r"(bf[j][2]), "=r"(bf[j][3])
                             : "r"(addr));
            }
            #pragma unroll
            for (int mi = 0; mi < 2; mi++)
                #pragma unroll
                for (int nj = 0; nj < 8; nj++) {
                    uint32_t b0 = bf[nj >> 1][(nj & 1) * 2 + 0];
                    uint32_t b1 = bf[nj >> 1][(nj & 1) * 2 + 1];
                    asm volatile(
                        "mma.sync.aligned.m16n8k16.row.col.f32.bf16.bf16.f32 "
                        "{%0,%1,%2,%3}, {%4,%5,%6,%7}, {%8,%9}, {%0,%1,%2,%3};"
                        : "+f"(acc[mi][nj][0]), "+f"(acc[mi][nj][1]),
                          "+f"(acc[mi][nj][2]), "+f"(acc[mi][nj][3])
                        : "r"(af[mi][0]), "r"(af[mi][1]), "r"(af[mi][2]), "r"(af[mi][3]),
                          "r"(b0), "r"(b1));
                }
        }
        __syncthreads();
    }

    // epilogue
    const int g = lane >> 2, tg = lane & 3;
    #pragma unroll
    for (int mi = 0; mi < 2; mi++) {
        int row0 = blk_m + warp_m * 32 + mi * 16 + g;
        #pragma unroll
        for (int nj = 0; nj < 8; nj++) {
            int col = blk_n + warp_n * 64 + nj * 8 + tg * 2;
            if (col >= N) continue;
            float b0 = __ldg(bias + col), b1 = __ldg(bias + col + 1);
            if (row0 < M) {
                float2 o = make_float2(acc[mi][nj][0] + b0, acc[mi][nj][1] + b1);
                *(float2*)(C + (size_t)row0 * N + col) = o;
            }
            if (row0 + 8 < M) {
                float2 o = make_float2(acc[mi][nj][2] + b0, acc[mi][nj][3] + b1);
                *(float2*)(C + (size_t)(row0 + 8) * N + col) = o;
            }
        }
    }
}

// ---------------- sampling: softmax + bilinear gather + weighted sum ----------------
// block = one query; warp = head, lane = channel. Setup lanes (<12) precompute
// tap indices + premultiplied weights; channel lanes do pure LDS/LDG/FFMA.
// Output written directly as bf16 hi|lo for the final GEMM.
__global__ __launch_bounds__(256) void sample_kernel(
    const float* __restrict__ value,       // [SEQ, 256]
    const float* __restrict__ raw,         // [SEQ, 288]
    const float* __restrict__ refp,        // [SEQ, 3, 2]
    __nv_bfloat16* __restrict__ outb,      // [SEQ, 512] hi|lo
    float* __restrict__ attn_out)          // [SEQ, 8, 12] or null
{
    const int q    = blockIdx.x;
    const int tid  = threadIdx.x;
    const int head = tid >> 5;
    const int lane = tid & 31;

    __shared__ __align__(16) int   s_idx[NATT][4];
    __shared__ __align__(16) float s_w  [NATT][4];

    const float* rq = raw + (size_t)q * N2;

    float logit = (lane < LP) ? rq[NOFF + head * LP + lane] : -INFINITY;
    float m = logit;
    #pragma unroll
    for (int o = 16; o; o >>= 1) m = fmaxf(m, __shfl_xor_sync(0xffffffffu, m, o));
    float e = (lane < LP) ? expf(logit - m) : 0.f;
    float s = e;
    #pragma unroll
    for (int o = 16; o; o >>= 1) s += __shfl_xor_sync(0xffffffffu, s, o);
    float a = e / s;

    if (lane < LP) {
        if (attn_out) attn_out[((size_t)q * NHEADS + head) * LP + lane] = a;

        const int l = lane >> 2;
        const int Wi = 160 >> l;
        const int start = (l == 0) ? 0 : ((l == 1) ? 25600 : 32000);
        const float dim = (float)Wi;

        const float ox = rq[(head * LP + lane) * 2 + 0];
        const float oy = rq[(head * LP + lane) * 2 + 1];
        const float rx = refp[((size_t)q * NLEVELS + l) * 2 + 0];
        const float ry = refp[((size_t)q * NLEVELS + l) * 2 + 1];
        const float px = (rx + ox / dim) * dim - 0.5f;
        const float py = (ry + oy / dim) * dim - 0.5f;

        const float x0f = floorf(px), y0f = floorf(py);
        const int   x0  = (int)x0f,   y0  = (int)y0f;
        const float wx1 = px - x0f, wy1 = py - y0f;
        const float wx0 = 1.f - wx1, wy0 = 1.f - wy1;

        const bool xok0 = (x0 >= 0)  && (x0 < Wi);
        const bool xok1 = (x0 >= -1) && (x0 + 1 < Wi);
        const bool yok0 = (y0 >= 0)  && (y0 < Wi);
        const bool yok1 = (y0 >= -1) && (y0 + 1 < Wi);

        const int base = start * DMODEL;
        const int r0 = y0 * Wi + x0;
        const int slot = head * LP + lane;

        s_idx[slot][0] = (xok0 && yok0) ? base + r0 * DMODEL            : 0;
        s_idx[slot][1] = (xok1 && yok0) ? base + (r0 + 1) * DMODEL      : 0;
        s_idx[slot][2] = (xok0 && yok1) ? base + (r0 + Wi) * DMODEL     : 0;
        s_idx[slot][3] = (xok1 && yok1) ? base + (r0 + Wi + 1) * DMODEL : 0;
        s_w[slot][0] = (xok0 && yok0) ? a * wy0 * wx0 : 0.f;
        s_w[slot][1] = (xok1 && yok0) ? a * wy0 * wx1 : 0.f;
        s_w[slot][2] = (xok0 && yok1) ? a * wy1 * wx0 : 0.f;
        s_w[slot][3] = (xok1 && yok1) ? a * wy1 * wx1 : 0.f;
    }
    __syncwarp();

    const float* vb = value + head * HD + lane;
    float acc = 0.f;
    #pragma unroll
    for (int lp = 0; lp < LP; lp++) {
        const int4   I  = *reinterpret_cast<const int4*>(s_idx[head * LP + lp]);
        const float4 W4 = *reinterpret_cast<const float4*>(s_w[head * LP + lp]);
        acc = fmaf(W4.x, __ldg(vb + I.x), acc);
        acc = fmaf(W4.y, __ldg(vb + I.y), acc);
        acc = fmaf(W4.z, __ldg(vb + I.z), acc);
        acc = fmaf(W4.w, __ldg(vb + I.w), acc);
    }

    __nv_bfloat16 hi, lo;
    split_bf16(acc, hi, lo);
    outb[(size_t)q * KHL + head * HD + lane]          = hi;
    outb[(size_t)q * KHL + DMODEL + head * HD + lane] = lo;
}

// ---------------- launch ----------------
extern "C" void kernel_launch(void* const* d_in, const int* in_sizes, int n_in,
                              void* d_out, int out_size)
{
    const float* hidden = (const float*)d_in[0];
    const float* enc    = (const float*)d_in[1];
    const float* pos    = (const float*)d_in[2];
    const float* refp   = (const float*)d_in[3];
    const float* Wv     = (const float*)d_in[4];
    const float* bv     = (const float*)d_in[5];
    const float* Ws     = (const float*)d_in[6];
    const float* bs     = (const float*)d_in[7];
    const float* Wa     = (const float*)d_in[8];
    const float* ba     = (const float*)d_in[9];
    const float* Wo     = (const float*)d_in[10];
    const float* bo     = (const float*)d_in[11];

    float* out = (float*)d_out;
    float* attn_ptr = ((size_t)out_size >= OUT_ELEMS + ATTN_ELEMS) ? (out + OUT_ELEMS) : nullptr;

    float *p_value, *p_raw, *p_w2, *p_b2;
    __nv_bfloat16 *p_encb, *p_hsb, *p_sampb, *p_wvb, *p_w2b, *p_wob;
    cudaGetSymbolAddress((void**)&p_value, g_value);
    cudaGetSymbolAddress((void**)&p_raw,   g_raw);
    cudaGetSymbolAddress((void**)&p_w2,    g_w2);
    cudaGetSymbolAddress((void**)&p_b2,    g_b2);
    cudaGetSymbolAddress((void**)&p_encb,  g_encb);
    cudaGetSymbolAddress((void**)&p_hsb,   g_hsb);
    cudaGetSymbolAddress((void**)&p_sampb, g_sampb);
    cudaGetSymbolAddress((void**)&p_wvb,   g_wvb);
    cudaGetSymbolAddress((void**)&p_w2b,   g_w2b);
    cudaGetSymbolAddress((void**)&p_wob,   g_wob);

    // 1) combine Ws/Wa
    build_w2_kernel<<<(N2 * DMODEL + 255) / 256, 256>>>(Ws, bs, Wa, ba);

    // 2) conversions to bf16 hi|lo
    conv_hilo_kernel<<<(DMODEL * 64 + 255) / 256, 256>>>(Wv,   nullptr, p_wvb, DMODEL);
    conv_hilo_kernel<<<(N2 * 64 + 255) / 256, 256>>>(p_w2,     nullptr, p_w2b, N2);
    conv_hilo_kernel<<<(DMODEL * 64 + 255) / 256, 256>>>(Wo,   nullptr, p_wob, DMODEL);
    conv_hilo_kernel<<<(SEQ * 64 + 255) / 256, 256>>>(enc,     nullptr, p_encb, SEQ);
    conv_hilo_kernel<<<(SEQ * 64 + 255) / 256, 256>>>(hidden,  pos,     p_hsb,  SEQ);

    const int grid_m = (SEQ + 127) / 128;   // 263

    // 3) value = enc @ Wv^T + bv
    {
        dim3 g(2, grid_m);
        gemm_bf16_kernel<<<g, 256>>>(p_encb, p_wvb, bv, p_value, SEQ, DMODEL);
    }
    // 4) raw = (hidden+pos) @ [Ws;Wa]^T + [bs;ba]
    {
        dim3 g(3, grid_m);
        gemm_bf16_kernel<<<g, 256>>>(p_hsb, p_w2b, p_b2, p_raw, SEQ, N2);
    }
    // 5) softmax + deformable sampling (emits bf16 hi|lo)
    sample_kernel<<<SEQ, 256>>>(p_value, p_raw, refp, p_sampb, attn_ptr);

    // 6) output = samp @ Wo^T + bo
    {
        dim3 g(2, grid_m);
        gemm_bf16_kernel<<<g, 256>>>(p_sampb, p_wob, bo, out, SEQ, DMODEL);
    }
}